// round 14
// baseline (speedup 1.0000x reference)
#include <cuda_runtime.h>
#include <cuda_bf16.h>
#include <cstdint>

#define NEG_INF (-1e30f)
#define BB 32
#define NN 256
#define KNB 20

// ---------------- packed fp32x2 helpers (maxfc path) ----------------
#define PACK_F32X2(out, lo, hi) \
    asm("mov.b64 %0, {%1, %2};" : "=l"(out) : "f"(lo), "f"(hi))
#define UNPACK_F32X2(lo, hi, in) \
    asm("mov.b64 {%0, %1}, %2;" : "=f"(lo), "=f"(hi) : "l"(in))
#define FMA_F32X2(d, a, b, c) \
    asm("fma.rn.f32x2 %0, %1, %2, %3;" : "=l"(d) : "l"(a), "l"(b), "l"(c))

// ---------------- mma.sync m16n8k16 bf16 + ldmatrix (baseline PTX) ----------
#define MMA16816(c, a0, a1, a2, a3, b0, b1) \
    asm volatile("mma.sync.aligned.m16n8k16.row.col.f32.bf16.bf16.f32 " \
        "{%0,%1,%2,%3}, {%4,%5,%6,%7}, {%8,%9}, {%0,%1,%2,%3};" \
        : "+f"((c)[0]), "+f"((c)[1]), "+f"((c)[2]), "+f"((c)[3]) \
        : "r"(a0), "r"(a1), "r"(a2), "r"(a3), "r"(b0), "r"(b1))

#define LDSM_X4(r0, r1, r2, r3, addr) \
    asm volatile("ldmatrix.sync.aligned.m8n8.x4.shared.b16 {%0,%1,%2,%3}, [%4];" \
        : "=r"(r0), "=r"(r1), "=r"(r2), "=r"(r3) : "r"(addr))

__device__ __forceinline__ uint32_t smem_u32(const void* p) {
    uint32_t a;
    asm("{ .reg .u64 t; cvta.to.shared.u64 t, %1; cvt.u32.u64 %0, t; }" : "=r"(a) : "l"(p));
    return a;
}

// ---------------- scratch globals ----------------
__device__ int            g_idx  [BB*NN*KNB];
__device__ float          g_H    [BB*NN*256];
__device__ __nv_bfloat16  g_H2hi [BB*NN*128];
__device__ __nv_bfloat16  g_H2lo [BB*NN*128];
__device__ __nv_bfloat16  g_w3hi [256*128];
__device__ __nv_bfloat16  g_w3lo [256*128];
__device__ float          g_w2T  [64*128];
__device__ float          g_w1T  [256*128];

// ---------------------------------------------------------------------------
// Kernel 0: weight prep (w2 transpose, fc1 transpose, w3 bf16 hi/lo split)
// ---------------------------------------------------------------------------
__global__ __launch_bounds__(256) void transpose_kernel(
    const float* __restrict__ w2, const float* __restrict__ w3,
    const float* __restrict__ fc1w)
{
    int tid = blockIdx.x*256 + threadIdx.x;
    if (tid < 8192) { int c = tid >> 7, o = tid & 127; g_w2T[tid] = w2[o*64 + c]; }
    int t2 = tid - 8192;
    if (t2 >= 0 && t2 < 32768) {
        float v = w3[t2];
        __nv_bfloat16 h = __float2bfloat16(v);
        __nv_bfloat16 l = __float2bfloat16(v - __bfloat162float(h));
        g_w3hi[t2] = h; g_w3lo[t2] = l;
    }
    int t3 = tid - 40960;
    if (t3 >= 0 && t3 < 32768) { int n = t3 >> 7, o = t3 & 127; g_w1T[t3] = fc1w[o*256 + n]; }
}

// ---------------------------------------------------------------------------
// Kernel 1: kNN (one row/warp, redux argmax)
// ---------------------------------------------------------------------------
__global__ __launch_bounds__(256) void knn_kernel(const float* __restrict__ x) {
    __shared__ float xs0[NN], xs1[NN], xs2[NN], xxs[NN];
    int b      = blockIdx.x >> 5;
    int n_base = (blockIdx.x & 31) * 8;
    int tid = threadIdx.x;
    {
        float a0 = x[(b*NN + tid)*3 + 0];
        float a1 = x[(b*NN + tid)*3 + 1];
        float a2 = x[(b*NN + tid)*3 + 2];
        xs0[tid] = a0; xs1[tid] = a1; xs2[tid] = a2;
        xxs[tid] = a0*a0 + a1*a1 + a2*a2;
    }
    __syncthreads();
    int w = tid >> 5, lane = tid & 31;
    int i = n_base + w;

    float xi0 = xs0[i], xi1 = xs1[i], xi2 = xs2[i], xxi = xxs[i];
    unsigned m[8];
    #pragma unroll
    for (int t = 0; t < 8; t++) {
        int j = lane + 32*t;
        float dv = 2.f*(xi0*xs0[j] + xi1*xs1[j] + xi2*xs2[j]) - xxi - xxs[j];
        unsigned u = __float_as_uint(dv);
        m[t] = u ^ (unsigned)(((int)u >> 31) | 0x80000000);
    }

    int myj = 0;
    #pragma unroll 4
    for (int kk = 0; kk < KNB; kk++) {
        unsigned bv = m[0]; int bj = lane;
        #pragma unroll
        for (int t = 1; t < 8; t++)
            if (m[t] > bv) { bv = m[t]; bj = lane + 32*t; }
        unsigned vmax = __reduce_max_sync(0xffffffffu, bv);
        unsigned cand = (bv == vmax) ? (unsigned)bj : 0x7fffffffu;
        int jwin = (int)__reduce_min_sync(0xffffffffu, cand);
        if (lane == kk) myj = jwin;
        if ((jwin & 31) == lane) {
            int t = jwin >> 5;
            #pragma unroll
            for (int tt = 0; tt < 8; tt++) if (tt == t) m[tt] = 0u;
        }
    }
    if (lane < KNB) g_idx[(b*NN + i)*KNB + lane] = myj;
}

// ---------------------------------------------------------------------------
// Kernel 2a: mlp12  3 -> 64 -> 128, emits H2 as bf16 hi/lo
// ---------------------------------------------------------------------------
#define MLP12_SMEM ((96 + 2048 + 8192)*4)
__global__ __launch_bounds__(256) void mlp12_kernel(
    const float* __restrict__ x,
    const float* __restrict__ w1, const float* __restrict__ s1, const float* __restrict__ t1,
    const float* __restrict__ s2, const float* __restrict__ t2)
{
    extern __shared__ float sm[];
    float* xs   = sm;
    float* H1s  = sm + 96;
    float* W2Ts = sm + 2144;

    int tid = threadIdx.x;
    int row_base = blockIdx.x * 32;
    int b = row_base >> 8;
    int j0 = row_base & 255;

    if (tid < 96) xs[tid] = x[b*768 + j0*3 + tid];
    for (int e = tid; e < 2048; e += 256)
        ((float4*)W2Ts)[e] = ((const float4*)g_w2T)[e];
    __syncthreads();

    int w = tid >> 5, lane = tid & 31;
    int rb = w * 4;

    {
        int o2 = lane + 32;
        float a0 = w1[lane*3], a1 = w1[lane*3+1], a2 = w1[lane*3+2];
        float b0 = w1[o2*3],   b1 = w1[o2*3+1],   b2 = w1[o2*3+2];
        float sa = s1[lane], ta = t1[lane], sb = s1[o2], tb = t1[o2];
        #pragma unroll
        for (int i = 0; i < 4; i++) {
            int row = rb + i;
            float x0 = xs[row*3], x1 = xs[row*3+1], x2 = xs[row*3+2];
            H1s[row*64 + lane]      = fmaxf(sa*(a0*x0 + a1*x1 + a2*x2) + ta, 0.f);
            H1s[row*64 + lane + 32] = fmaxf(sb*(b0*x0 + b1*x1 + b2*x2) + tb, 0.f);
        }
    }
    __syncthreads();

    float acc[4][4];
    #pragma unroll
    for (int i = 0; i < 4; i++)
        #pragma unroll
        for (int k = 0; k < 4; k++) acc[i][k] = 0.f;
    #pragma unroll 8
    for (int c = 0; c < 64; c++) {
        float4 wv = *(const float4*)&W2Ts[c*128 + lane*4];
        #pragma unroll
        for (int i = 0; i < 4; i++) {
            float h = H1s[(rb+i)*64 + c];
            acc[i][0] += h*wv.x; acc[i][1] += h*wv.y;
            acc[i][2] += h*wv.z; acc[i][3] += h*wv.w;
        }
    }
    float sv[4], tv[4];
    #pragma unroll
    for (int k = 0; k < 4; k++) { sv[k] = s2[lane*4+k]; tv[k] = t2[lane*4+k]; }
    #pragma unroll
    for (int i = 0; i < 4; i++) {
        float o[4];
        #pragma unroll
        for (int k = 0; k < 4; k++)
            o[k] = fmaxf(sv[k]*acc[i][k] + tv[k], 0.f);
        __nv_bfloat16 h[4], l[4];
        #pragma unroll
        for (int k = 0; k < 4; k++) {
            h[k] = __float2bfloat16(o[k]);
            l[k] = __float2bfloat16(o[k] - __bfloat162float(h[k]));
        }
        int base = (row_base + rb + i)*128 + lane*4;
        ((__nv_bfloat162*)(g_H2hi + base))[0] = __halves2bfloat162(h[0], h[1]);
        ((__nv_bfloat162*)(g_H2hi + base))[1] = __halves2bfloat162(h[2], h[3]);
        ((__nv_bfloat162*)(g_H2lo + base))[0] = __halves2bfloat162(l[0], l[1]);
        ((__nv_bfloat162*)(g_H2lo + base))[1] = __halves2bfloat162(l[2], l[3]);
    }
}

// ---------------------------------------------------------------------------
// Kernel 2b: mlp3 via mma.sync + ldmatrix (HMMA bf16, hi/lo split, 3 passes).
// grid = 256 blocks (64-row groups x 2 o-halves), 256 threads, 2 CTA/SM.
// Warp = (16-row m-tile) x (64-col n-half): warps laid 4(m) x 2(n).
// Per k-step: 2 A ldmatrix.x4 (hi/lo) + 8 B ldmatrix.x4 (4 nt-pairs x hi/lo).
// ---------------------------------------------------------------------------
#define AHI_OFF 0
#define ALO_OFF 17408
#define BHI_OFF 34816
#define BLO_OFF 69632
#define S3H_OFF 104448
#define T3H_OFF 104960
#define MLP3H_SMEM 105472

__global__ __launch_bounds__(256, 2) void mlp3h_kernel(
    const float* __restrict__ s3, const float* __restrict__ t3)
{
    extern __shared__ char smc[];
    int tid = threadIdx.x;
    int w = tid >> 5, lane = tid & 31;
    int g = lane >> 2, tig = lane & 3;
    int bid = blockIdx.x;
    int row0 = (bid >> 1) * 64;
    int oh = bid & 1;

    // stage A (H2 hi/lo): 64 rows x 128 bf16 = 16 uint4 per row, padded rows (272B)
    for (int e = tid; e < 1024; e += 256) {
        int row = e >> 4, q = e & 15;
        *(uint4*)(smc + AHI_OFF + row*272 + q*16) =
            ((const uint4*)(g_H2hi + (row0 + row)*128))[q];
        *(uint4*)(smc + ALO_OFF + row*272 + q*16) =
            ((const uint4*)(g_H2lo + (row0 + row)*128))[q];
    }
    // stage B (w3 hi/lo, this o-half): 128 rows x 128 bf16 = 16 uint4 per row
    for (int e = tid; e < 2048; e += 256) {
        int row = e >> 4, q = e & 15;
        *(uint4*)(smc + BHI_OFF + row*272 + q*16) =
            ((const uint4*)(g_w3hi + (oh*128 + row)*128))[q];
        *(uint4*)(smc + BLO_OFF + row*272 + q*16) =
            ((const uint4*)(g_w3lo + (oh*128 + row)*128))[q];
    }
    if (tid < 128) {
        *(float*)(smc + S3H_OFF + tid*4) = s3[oh*128 + tid];
        *(float*)(smc + T3H_OFF + tid*4) = t3[oh*128 + tid];
    }
    __syncthreads();

    int m0 = (w >> 1) * 16;    // m-tile rows within the 64-row group
    int nb = (w & 1) * 64;     // n-half within the 128-col o-half

    uint32_t smb = smem_u32(smc);
    // A ldmatrix lane address: rows m0 + (lane&7) + ((lane>>3)&1)*8, k-half (lane>>4)*16B
    uint32_t a_row_off = (uint32_t)((m0 + (lane & 7) + ((lane >> 3) & 1)*8) * 272
                                    + (lane >> 4) * 16);
    uint32_t aaddr_hi = smb + AHI_OFF + a_row_off;
    uint32_t aaddr_lo = smb + ALO_OFF + a_row_off;
    // B ldmatrix lane address (tile pair p adds p*16*272): t0/t1 = nt_even rows (k0,+16B),
    // t2/t3 = nt_odd rows: row_add = ((lane>>4)&1)*8 + (lane&7); kbyte = ((lane>>3)&1)*16
    uint32_t b_row_off = (uint32_t)((nb + ((lane >> 4) & 1)*8 + (lane & 7)) * 272
                                    + ((lane >> 3) & 1) * 16);
    uint32_t baddr_hi = smb + BHI_OFF + b_row_off;
    uint32_t baddr_lo = smb + BLO_OFF + b_row_off;

    float acc[8][4];
    #pragma unroll
    for (int nt = 0; nt < 8; nt++)
        #pragma unroll
        for (int k = 0; k < 4; k++) acc[nt][k] = 0.f;

    #pragma unroll
    for (int k0 = 0; k0 < 128; k0 += 16) {
        uint32_t ah0, ah1, ah2, ah3, al0, al1, al2, al3;
        LDSM_X4(ah0, ah1, ah2, ah3, aaddr_hi);
        LDSM_X4(al0, al1, al2, al3, aaddr_lo);
        aaddr_hi += 32; aaddr_lo += 32;
        #pragma unroll
        for (int p = 0; p < 4; p++) {
            uint32_t bh0, bh1, bh2, bh3, bl0, bl1, bl2, bl3;
            LDSM_X4(bh0, bh1, bh2, bh3, baddr_hi + p*4352u);
            LDSM_X4(bl0, bl1, bl2, bl3, baddr_lo + p*4352u);
            MMA16816(acc[2*p],   ah0, ah1, ah2, ah3, bh0, bh1);
            MMA16816(acc[2*p],   ah0, ah1, ah2, ah3, bl0, bl1);
            MMA16816(acc[2*p],   al0, al1, al2, al3, bh0, bh1);
            MMA16816(acc[2*p+1], ah0, ah1, ah2, ah3, bh2, bh3);
            MMA16816(acc[2*p+1], ah0, ah1, ah2, ah3, bl2, bl3);
            MMA16816(acc[2*p+1], al0, al1, al2, al3, bh2, bh3);
        }
        baddr_hi += 32; baddr_lo += 32;
    }

    // epilogue: scale + shift + relu, direct f32 stores (pairs are contiguous)
    #pragma unroll
    for (int nt = 0; nt < 8; nt++) {
        int ci = nb + nt*8 + 2*tig;                 // col within o-half
        float2 sv = *(const float2*)(smc + S3H_OFF + ci*4);
        float2 tv = *(const float2*)(smc + T3H_OFF + ci*4);
        float2 o0, o1;
        o0.x = fmaxf(sv.x*acc[nt][0] + tv.x, 0.f);
        o0.y = fmaxf(sv.y*acc[nt][1] + tv.y, 0.f);
        o1.x = fmaxf(sv.x*acc[nt][2] + tv.x, 0.f);
        o1.y = fmaxf(sv.y*acc[nt][3] + tv.y, 0.f);
        int col = oh*128 + ci;
        *(float2*)&g_H[(row0 + m0 + g)*256 + col]     = o0;
        *(float2*)&g_H[(row0 + m0 + g + 8)*256 + col] = o1;
    }
}

// ---------------------------------------------------------------------------
// Kernel 3: FUSED gather-max + fc1 + fc2 (round-13 exact, f32x2 fc1)
// ---------------------------------------------------------------------------
#define MAXFC_SMEM ((16384 + 32768 + 5120)*4)
__global__ __launch_bounds__(512) void maxfc_kernel(
    const float* __restrict__ fc1_b,
    const float* __restrict__ fc2_w, const float* __restrict__ fc2_b,
    float* __restrict__ out)
{
    extern __shared__ float sm[];
    float* Ms   = sm;           // [n 256][c 64]
    float* Hs   = sm + 16384;   // [j 256][c 64]  (phase A)
    float* W1Ts = sm + 16384;   // [n 256][o 128] (phase B overlay)
    float* W2s  = sm + 49152;   // [q 40][o 128]
    int b = blockIdx.x >> 2, ct = blockIdx.x & 3;
    int tid = threadIdx.x;
    int w = tid >> 5, lane = tid & 31;

    for (int e = tid; e < 4096; e += 512) {
        int j = e >> 4, q = e & 15;
        ((float4*)Hs)[e] = *(const float4*)(g_H + (b*256 + j)*256 + ct*64 + q*4);
    }
    __syncthreads();

    #pragma unroll 2
    for (int t = 0; t < 16; t += 2) {
        int n0 = w*16 + t, n1 = n0 + 1;
        const int4* ip0 = (const int4*)(g_idx + (b*NN + n0)*KNB);
        const int4* ip1 = (const int4*)(g_idx + (b*NN + n1)*KNB);
        float a0 = NEG_INF, a1 = NEG_INF, c0 = NEG_INF, c1 = NEG_INF;
        #pragma unroll
        for (int q = 0; q < 5; q++) {
            int4 u = ip0[q];
            int4 v = ip1[q];
            a0 = fmaxf(a0, Hs[u.x*64 + lane]); a1 = fmaxf(a1, Hs[u.x*64 + lane + 32]);
            c0 = fmaxf(c0, Hs[v.x*64 + lane]); c1 = fmaxf(c1, Hs[v.x*64 + lane + 32]);
            a0 = fmaxf(a0, Hs[u.y*64 + lane]); a1 = fmaxf(a1, Hs[u.y*64 + lane + 32]);
            c0 = fmaxf(c0, Hs[v.y*64 + lane]); c1 = fmaxf(c1, Hs[v.y*64 + lane + 32]);
            a0 = fmaxf(a0, Hs[u.z*64 + lane]); a1 = fmaxf(a1, Hs[u.z*64 + lane + 32]);
            c0 = fmaxf(c0, Hs[v.z*64 + lane]); c1 = fmaxf(c1, Hs[v.z*64 + lane + 32]);
            a0 = fmaxf(a0, Hs[u.w*64 + lane]); a1 = fmaxf(a1, Hs[u.w*64 + lane + 32]);
            c0 = fmaxf(c0, Hs[v.w*64 + lane]); c1 = fmaxf(c1, Hs[v.w*64 + lane + 32]);
        }
        Ms[n0*64 + lane] = a0; Ms[n0*64 + lane + 32] = a1;
        Ms[n1*64 + lane] = c0; Ms[n1*64 + lane + 32] = c1;
    }
    __syncthreads();

    for (int e = tid; e < 8192; e += 512)
        ((float4*)W1Ts)[e] = ((const float4*)g_w1T)[e];
    for (int e = tid; e < 1280; e += 512)
        ((float4*)W2s)[e] = ((const float4*)fc2_w)[e];
    __syncthreads();

    int half = w >> 3, w8 = w & 7;
    int o_base = w8*16 + (lane >> 4)*8;
    int c_base = (lane & 15)*4;

    unsigned long long A[4][4];
    #pragma unroll
    for (int i = 0; i < 4; i++)
        #pragma unroll
        for (int p = 0; p < 4; p++) A[i][p] = 0ull;

    int n0 = half*128;
    #pragma unroll 4
    for (int n = n0; n < n0 + 128; n++) {
        float4 mv = *(const float4*)&Ms[n*64 + c_base];
        float4 wa = *(const float4*)&W1Ts[n*128 + o_base];
        float4 wb = *(const float4*)&W1Ts[n*128 + o_base + 4];
        unsigned long long wp[4];
        PACK_F32X2(wp[0], wa.x, wa.y);
        PACK_F32X2(wp[1], wa.z, wa.w);
        PACK_F32X2(wp[2], wb.x, wb.y);
        PACK_F32X2(wp[3], wb.z, wb.w);
        float mm[4] = {mv.x, mv.y, mv.z, mv.w};
        #pragma unroll
        for (int i = 0; i < 4; i++) {
            unsigned long long md;
            PACK_F32X2(md, mm[i], mm[i]);
            #pragma unroll
            for (int p = 0; p < 4; p++)
                FMA_F32X2(A[i][p], md, wp[p], A[i][p]);
        }
    }
    float acc[4][8];
    #pragma unroll
    for (int i = 0; i < 4; i++)
        #pragma unroll
        for (int p = 0; p < 4; p++)
            UNPACK_F32X2(acc[i][2*p], acc[i][2*p+1], A[i][p]);
    __syncthreads();

    float* Rs = sm;
    float* Gs = sm + 8320;
    if (half == 1) {
        #pragma unroll
        for (int i = 0; i < 4; i++)
            #pragma unroll
            for (int k = 0; k < 8; k++)
                Rs[(c_base + i)*129 + o_base + k] = acc[i][k];
    }
    __syncthreads();
    if (half == 0) {
        float b1v[8];
        #pragma unroll
        for (int k = 0; k < 8; k++) b1v[k] = fc1_b[o_base + k];
        #pragma unroll
        for (int i = 0; i < 4; i++)
            #pragma unroll
            for (int k = 0; k < 8; k++)
                Gs[(c_base + i)*129 + o_base + k] =
                    fmaxf(acc[i][k] + Rs[(c_base + i)*129 + o_base + k] + b1v[k], 0.f);
    }
    __syncthreads();

    if (w < 8) {
        float acc2[2][5];
        #pragma unroll
        for (int h = 0; h < 2; h++)
            #pragma unroll
            for (int q = 0; q < 5; q++) acc2[h][q] = 0.f;
        #pragma unroll 4
        for (int o = 0; o < 128; o++) {
            float ga = Gs[lane*129 + o];
            float gb = Gs[(lane + 32)*129 + o];
            #pragma unroll
            for (int q = 0; q < 5; q++) {
                float wv = W2s[(w*5 + q)*128 + o];
                acc2[0][q] += ga*wv;
                acc2[1][q] += gb*wv;
            }
        }
        #pragma unroll
        for (int h = 0; h < 2; h++) {
            int cg = ct*64 + lane + h*32;
            #pragma unroll
            for (int q = 0; q < 5; q++)
                out[(b*256 + cg)*40 + w*5 + q] = acc2[h][q] + fc2_b[w*5 + q];
        }
    }
}

extern "C" void kernel_launch(void* const* d_in, const int* in_sizes, int n_in,
                              void* d_out, int out_size) {
    const float* x    = (const float*)d_in[0];
    const float* w1   = (const float*)d_in[1];
    const float* s1   = (const float*)d_in[2];
    const float* t1   = (const float*)d_in[3];
    const float* w2   = (const float*)d_in[4];
    const float* s2   = (const float*)d_in[5];
    const float* t2   = (const float*)d_in[6];
    const float* w3   = (const float*)d_in[7];
    const float* s3   = (const float*)d_in[8];
    const float* t3   = (const float*)d_in[9];
    const float* fc1w = (const float*)d_in[10];
    const float* fc1b = (const float*)d_in[11];
    const float* fc2w = (const float*)d_in[12];
    const float* fc2b = (const float*)d_in[13];
    float* out = (float*)d_out;

    cudaFuncSetAttribute(mlp12_kernel, cudaFuncAttributeMaxDynamicSharedMemorySize, MLP12_SMEM);
    cudaFuncSetAttribute(mlp3h_kernel, cudaFuncAttributeMaxDynamicSharedMemorySize, MLP3H_SMEM);
    cudaFuncSetAttribute(maxfc_kernel, cudaFuncAttributeMaxDynamicSharedMemorySize, MAXFC_SMEM);

    transpose_kernel<<<288, 256>>>(w2, w3, fc1w);
    knn_kernel<<<1024, 256>>>(x);
    mlp12_kernel<<<256, 256, MLP12_SMEM>>>(x, w1, s1, t1, s2, t2);
    mlp3h_kernel<<<256, 256, MLP3H_SMEM>>>(s3, t3);
    maxfc_kernel<<<128, 512, MAXFC_SMEM>>>(fc1b, fc2w, fc2b, out);
}

// round 15
// speedup vs baseline: 1.1868x; 1.1868x over previous
#include <cuda_runtime.h>
#include <cuda_bf16.h>
#include <cstdint>

#define NEG_INF (-1e30f)
#define BB 32
#define NN 256
#define KNB 20

// ---------------- mma.sync m16n8k16 bf16 + ldmatrix (baseline PTX) ----------
#define MMA16816(c, a0, a1, a2, a3, b0, b1) \
    asm volatile("mma.sync.aligned.m16n8k16.row.col.f32.bf16.bf16.f32 " \
        "{%0,%1,%2,%3}, {%4,%5,%6,%7}, {%8,%9}, {%0,%1,%2,%3};" \
        : "+f"((c)[0]), "+f"((c)[1]), "+f"((c)[2]), "+f"((c)[3]) \
        : "r"(a0), "r"(a1), "r"(a2), "r"(a3), "r"(b0), "r"(b1))

#define LDSM_X4(r0, r1, r2, r3, addr) \
    asm volatile("ldmatrix.sync.aligned.m8n8.x4.shared.b16 {%0,%1,%2,%3}, [%4];" \
        : "=r"(r0), "=r"(r1), "=r"(r2), "=r"(r3) : "r"(addr))

__device__ __forceinline__ uint32_t smem_u32(const void* p) {
    uint32_t a;
    asm("{ .reg .u64 t; cvta.to.shared.u64 t, %1; cvt.u32.u64 %0, t; }" : "=r"(a) : "l"(p));
    return a;
}

// ---------------- scratch globals ----------------
__device__ int            g_idx  [BB*NN*KNB];
__device__ float          g_H    [BB*NN*256];
__device__ __nv_bfloat16  g_H2hi [BB*NN*128];
__device__ __nv_bfloat16  g_H2lo [BB*NN*128];
__device__ __nv_bfloat16  g_w3hi [256*128];
__device__ __nv_bfloat16  g_w3lo [256*128];
__device__ __nv_bfloat16  g_w1hi [128*256];
__device__ __nv_bfloat16  g_w1lo [128*256];
__device__ float          g_w2T  [64*128];

// ---------------------------------------------------------------------------
// Kernel 0: weight prep (w2 transpose; w3 and fc1_w bf16 hi/lo splits)
// ---------------------------------------------------------------------------
__global__ __launch_bounds__(256) void transpose_kernel(
    const float* __restrict__ w2, const float* __restrict__ w3,
    const float* __restrict__ fc1w)
{
    int tid = blockIdx.x*256 + threadIdx.x;
    if (tid < 8192) { int c = tid >> 7, o = tid & 127; g_w2T[tid] = w2[o*64 + c]; }
    int t2 = tid - 8192;
    if (t2 >= 0 && t2 < 32768) {
        float v = w3[t2];
        __nv_bfloat16 h = __float2bfloat16(v);
        __nv_bfloat16 l = __float2bfloat16(v - __bfloat162float(h));
        g_w3hi[t2] = h; g_w3lo[t2] = l;
    }
    int t3 = tid - 40960;
    if (t3 >= 0 && t3 < 32768) {
        float v = fc1w[t3];               // already [o][n]
        __nv_bfloat16 h = __float2bfloat16(v);
        __nv_bfloat16 l = __float2bfloat16(v - __bfloat162float(h));
        g_w1hi[t3] = h; g_w1lo[t3] = l;
    }
}

// ---------------------------------------------------------------------------
// Kernel 1: kNN (one row/warp, redux argmax)
// ---------------------------------------------------------------------------
__global__ __launch_bounds__(256) void knn_kernel(const float* __restrict__ x) {
    __shared__ float xs0[NN], xs1[NN], xs2[NN], xxs[NN];
    int b      = blockIdx.x >> 5;
    int n_base = (blockIdx.x & 31) * 8;
    int tid = threadIdx.x;
    {
        float a0 = x[(b*NN + tid)*3 + 0];
        float a1 = x[(b*NN + tid)*3 + 1];
        float a2 = x[(b*NN + tid)*3 + 2];
        xs0[tid] = a0; xs1[tid] = a1; xs2[tid] = a2;
        xxs[tid] = a0*a0 + a1*a1 + a2*a2;
    }
    __syncthreads();
    int w = tid >> 5, lane = tid & 31;
    int i = n_base + w;

    float xi0 = xs0[i], xi1 = xs1[i], xi2 = xs2[i], xxi = xxs[i];
    unsigned m[8];
    #pragma unroll
    for (int t = 0; t < 8; t++) {
        int j = lane + 32*t;
        float dv = 2.f*(xi0*xs0[j] + xi1*xs1[j] + xi2*xs2[j]) - xxi - xxs[j];
        unsigned u = __float_as_uint(dv);
        m[t] = u ^ (unsigned)(((int)u >> 31) | 0x80000000);
    }

    int myj = 0;
    #pragma unroll 4
    for (int kk = 0; kk < KNB; kk++) {
        unsigned bv = m[0]; int bj = lane;
        #pragma unroll
        for (int t = 1; t < 8; t++)
            if (m[t] > bv) { bv = m[t]; bj = lane + 32*t; }
        unsigned vmax = __reduce_max_sync(0xffffffffu, bv);
        unsigned cand = (bv == vmax) ? (unsigned)bj : 0x7fffffffu;
        int jwin = (int)__reduce_min_sync(0xffffffffu, cand);
        if (lane == kk) myj = jwin;
        if ((jwin & 31) == lane) {
            int t = jwin >> 5;
            #pragma unroll
            for (int tt = 0; tt < 8; tt++) if (tt == t) m[tt] = 0u;
        }
    }
    if (lane < KNB) g_idx[(b*NN + i)*KNB + lane] = myj;
}

// ---------------------------------------------------------------------------
// Kernel 2a: mlp12  3 -> 64 -> 128, emits H2 as bf16 hi/lo
// ---------------------------------------------------------------------------
#define MLP12_SMEM ((96 + 2048 + 8192)*4)
__global__ __launch_bounds__(256) void mlp12_kernel(
    const float* __restrict__ x,
    const float* __restrict__ w1, const float* __restrict__ s1, const float* __restrict__ t1,
    const float* __restrict__ s2, const float* __restrict__ t2)
{
    extern __shared__ float sm[];
    float* xs   = sm;
    float* H1s  = sm + 96;
    float* W2Ts = sm + 2144;

    int tid = threadIdx.x;
    int row_base = blockIdx.x * 32;
    int b = row_base >> 8;
    int j0 = row_base & 255;

    if (tid < 96) xs[tid] = x[b*768 + j0*3 + tid];
    for (int e = tid; e < 2048; e += 256)
        ((float4*)W2Ts)[e] = ((const float4*)g_w2T)[e];
    __syncthreads();

    int w = tid >> 5, lane = tid & 31;
    int rb = w * 4;

    {
        int o2 = lane + 32;
        float a0 = w1[lane*3], a1 = w1[lane*3+1], a2 = w1[lane*3+2];
        float b0 = w1[o2*3],   b1 = w1[o2*3+1],   b2 = w1[o2*3+2];
        float sa = s1[lane], ta = t1[lane], sb = s1[o2], tb = t1[o2];
        #pragma unroll
        for (int i = 0; i < 4; i++) {
            int row = rb + i;
            float x0 = xs[row*3], x1 = xs[row*3+1], x2 = xs[row*3+2];
            H1s[row*64 + lane]      = fmaxf(sa*(a0*x0 + a1*x1 + a2*x2) + ta, 0.f);
            H1s[row*64 + lane + 32] = fmaxf(sb*(b0*x0 + b1*x1 + b2*x2) + tb, 0.f);
        }
    }
    __syncthreads();

    float acc[4][4];
    #pragma unroll
    for (int i = 0; i < 4; i++)
        #pragma unroll
        for (int k = 0; k < 4; k++) acc[i][k] = 0.f;
    #pragma unroll 8
    for (int c = 0; c < 64; c++) {
        float4 wv = *(const float4*)&W2Ts[c*128 + lane*4];
        #pragma unroll
        for (int i = 0; i < 4; i++) {
            float h = H1s[(rb+i)*64 + c];
            acc[i][0] += h*wv.x; acc[i][1] += h*wv.y;
            acc[i][2] += h*wv.z; acc[i][3] += h*wv.w;
        }
    }
    float sv[4], tv[4];
    #pragma unroll
    for (int k = 0; k < 4; k++) { sv[k] = s2[lane*4+k]; tv[k] = t2[lane*4+k]; }
    #pragma unroll
    for (int i = 0; i < 4; i++) {
        float o[4];
        #pragma unroll
        for (int k = 0; k < 4; k++)
            o[k] = fmaxf(sv[k]*acc[i][k] + tv[k], 0.f);
        __nv_bfloat16 h[4], l[4];
        #pragma unroll
        for (int k = 0; k < 4; k++) {
            h[k] = __float2bfloat16(o[k]);
            l[k] = __float2bfloat16(o[k] - __bfloat162float(h[k]));
        }
        int base = (row_base + rb + i)*128 + lane*4;
        ((__nv_bfloat162*)(g_H2hi + base))[0] = __halves2bfloat162(h[0], h[1]);
        ((__nv_bfloat162*)(g_H2hi + base))[1] = __halves2bfloat162(h[2], h[3]);
        ((__nv_bfloat162*)(g_H2lo + base))[0] = __halves2bfloat162(l[0], l[1]);
        ((__nv_bfloat162*)(g_H2lo + base))[1] = __halves2bfloat162(l[2], l[3]);
    }
}

// ---------------------------------------------------------------------------
// Kernel 2b: mlp3 via mma.sync + ldmatrix (round-14 exact)
// ---------------------------------------------------------------------------
#define AHI_OFF 0
#define ALO_OFF 17408
#define BHI_OFF 34816
#define BLO_OFF 69632
#define S3H_OFF 104448
#define T3H_OFF 104960
#define MLP3H_SMEM 105472

__global__ __launch_bounds__(256, 2) void mlp3h_kernel(
    const float* __restrict__ s3, const float* __restrict__ t3)
{
    extern __shared__ char smc[];
    int tid = threadIdx.x;
    int w = tid >> 5, lane = tid & 31;
    int g = lane >> 2, tig = lane & 3;
    int bid = blockIdx.x;
    int row0 = (bid >> 1) * 64;
    int oh = bid & 1;

    for (int e = tid; e < 1024; e += 256) {
        int row = e >> 4, q = e & 15;
        *(uint4*)(smc + AHI_OFF + row*272 + q*16) =
            ((const uint4*)(g_H2hi + (row0 + row)*128))[q];
        *(uint4*)(smc + ALO_OFF + row*272 + q*16) =
            ((const uint4*)(g_H2lo + (row0 + row)*128))[q];
    }
    for (int e = tid; e < 2048; e += 256) {
        int row = e >> 4, q = e & 15;
        *(uint4*)(smc + BHI_OFF + row*272 + q*16) =
            ((const uint4*)(g_w3hi + (oh*128 + row)*128))[q];
        *(uint4*)(smc + BLO_OFF + row*272 + q*16) =
            ((const uint4*)(g_w3lo + (oh*128 + row)*128))[q];
    }
    if (tid < 128) {
        *(float*)(smc + S3H_OFF + tid*4) = s3[oh*128 + tid];
        *(float*)(smc + T3H_OFF + tid*4) = t3[oh*128 + tid];
    }
    __syncthreads();

    int m0 = (w >> 1) * 16;
    int nb = (w & 1) * 64;

    uint32_t smb = smem_u32(smc);
    uint32_t a_row_off = (uint32_t)((m0 + (lane & 7) + ((lane >> 3) & 1)*8) * 272
                                    + (lane >> 4) * 16);
    uint32_t aaddr_hi = smb + AHI_OFF + a_row_off;
    uint32_t aaddr_lo = smb + ALO_OFF + a_row_off;
    uint32_t b_row_off = (uint32_t)((nb + ((lane >> 4) & 1)*8 + (lane & 7)) * 272
                                    + ((lane >> 3) & 1) * 16);
    uint32_t baddr_hi = smb + BHI_OFF + b_row_off;
    uint32_t baddr_lo = smb + BLO_OFF + b_row_off;

    float acc[8][4];
    #pragma unroll
    for (int nt = 0; nt < 8; nt++)
        #pragma unroll
        for (int k = 0; k < 4; k++) acc[nt][k] = 0.f;

    #pragma unroll
    for (int k0 = 0; k0 < 128; k0 += 16) {
        uint32_t ah0, ah1, ah2, ah3, al0, al1, al2, al3;
        LDSM_X4(ah0, ah1, ah2, ah3, aaddr_hi);
        LDSM_X4(al0, al1, al2, al3, aaddr_lo);
        aaddr_hi += 32; aaddr_lo += 32;
        #pragma unroll
        for (int p = 0; p < 4; p++) {
            uint32_t bh0, bh1, bh2, bh3, bl0, bl1, bl2, bl3;
            LDSM_X4(bh0, bh1, bh2, bh3, baddr_hi + p*4352u);
            LDSM_X4(bl0, bl1, bl2, bl3, baddr_lo + p*4352u);
            MMA16816(acc[2*p],   ah0, ah1, ah2, ah3, bh0, bh1);
            MMA16816(acc[2*p],   ah0, ah1, ah2, ah3, bl0, bl1);
            MMA16816(acc[2*p],   al0, al1, al2, al3, bh0, bh1);
            MMA16816(acc[2*p+1], ah0, ah1, ah2, ah3, bh2, bh3);
            MMA16816(acc[2*p+1], ah0, ah1, ah2, ah3, bl2, bl3);
            MMA16816(acc[2*p+1], al0, al1, al2, al3, bh2, bh3);
        }
        baddr_hi += 32; baddr_lo += 32;
    }

    #pragma unroll
    for (int nt = 0; nt < 8; nt++) {
        int ci = nb + nt*8 + 2*tig;
        float2 sv = *(const float2*)(smc + S3H_OFF + ci*4);
        float2 tv = *(const float2*)(smc + T3H_OFF + ci*4);
        float2 o0, o1;
        o0.x = fmaxf(sv.x*acc[nt][0] + tv.x, 0.f);
        o0.y = fmaxf(sv.y*acc[nt][1] + tv.y, 0.f);
        o1.x = fmaxf(sv.x*acc[nt][2] + tv.x, 0.f);
        o1.y = fmaxf(sv.y*acc[nt][3] + tv.y, 0.f);
        int col = oh*128 + ci;
        *(float2*)&g_H[(row0 + m0 + g)*256 + col]     = o0;
        *(float2*)&g_H[(row0 + m0 + g + 8)*256 + col] = o1;
    }
}

// ---------------------------------------------------------------------------
// Kernel 3: FUSED gather-max + fc1(HMMA bf16 hi/lo) + fc2.
// grid = 128 (32 b x 4 ch-tiles of 64), 512 threads, 1 CTA/SM.
// A = Ms [64 ch][256 n] bf16 hi/lo, written directly by gather (stride 528B).
// B = fc1_w [128 o][256 n] bf16 hi/lo (stride 528B) -> plain ldmatrix.
// smem map (bytes):
//   A_hi 0..33792 | A_lo 33792..67584 | Hs(f32, phase A) / W1hi (phase B) 67584..135168
//   W1lo 135168..202752 | W2s 202752..223232 | fc1_b 223232..223744
//   Gs (fc2 input, [64][129] f32) overlays A after MMA phase.
// ---------------------------------------------------------------------------
#define MFA_HI  0
#define MFA_LO  33792
#define MFHS    67584
#define MFW1HI  67584
#define MFW1LO  135168
#define MFW2    202752
#define MFB1    223232
#define MAXFC_SMEM 223744

__global__ __launch_bounds__(512) void maxfc_kernel(
    const float* __restrict__ fc1_b,
    const float* __restrict__ fc2_w, const float* __restrict__ fc2_b,
    float* __restrict__ out)
{
    extern __shared__ char smc[];
    float* Hs  = (float*)(smc + MFHS);     // [j 256][c 64]
    float* W2s = (float*)(smc + MFW2);     // [q 40][o 128]
    int b = blockIdx.x >> 2, ct = blockIdx.x & 3;
    int tid = threadIdx.x;
    int w = tid >> 5, lane = tid & 31;
    int g = lane >> 2, tig = lane & 3;

    // ---- Phase A: stage H channel-slice + small tensors
    for (int e = tid; e < 4096; e += 512) {
        int j = e >> 4, q = e & 15;
        ((float4*)Hs)[e] = *(const float4*)(g_H + (b*256 + j)*256 + ct*64 + q*4);
    }
    for (int e = tid; e < 1280; e += 512)
        ((float4*)W2s)[e] = ((const float4*)fc2_w)[e];
    if (tid < 128) *(float*)(smc + MFB1 + tid*4) = fc1_b[tid];
    __syncthreads();

    // ---- gather-max; write A = Ms^T directly as bf16 hi/lo [ch][n], stride 528B
    #pragma unroll 2
    for (int t = 0; t < 16; t += 2) {
        int n0 = w*16 + t, n1 = n0 + 1;
        const int4* ip0 = (const int4*)(g_idx + (b*NN + n0)*KNB);
        const int4* ip1 = (const int4*)(g_idx + (b*NN + n1)*KNB);
        float a0 = NEG_INF, a1 = NEG_INF, c0 = NEG_INF, c1 = NEG_INF;
        #pragma unroll
        for (int q = 0; q < 5; q++) {
            int4 u = ip0[q];
            int4 v = ip1[q];
            a0 = fmaxf(a0, Hs[u.x*64 + lane]); a1 = fmaxf(a1, Hs[u.x*64 + lane + 32]);
            c0 = fmaxf(c0, Hs[v.x*64 + lane]); c1 = fmaxf(c1, Hs[v.x*64 + lane + 32]);
            a0 = fmaxf(a0, Hs[u.y*64 + lane]); a1 = fmaxf(a1, Hs[u.y*64 + lane + 32]);
            c0 = fmaxf(c0, Hs[v.y*64 + lane]); c1 = fmaxf(c1, Hs[v.y*64 + lane + 32]);
            a0 = fmaxf(a0, Hs[u.z*64 + lane]); a1 = fmaxf(a1, Hs[u.z*64 + lane + 32]);
            c0 = fmaxf(c0, Hs[v.z*64 + lane]); c1 = fmaxf(c1, Hs[v.z*64 + lane + 32]);
            a0 = fmaxf(a0, Hs[u.w*64 + lane]); a1 = fmaxf(a1, Hs[u.w*64 + lane + 32]);
            c0 = fmaxf(c0, Hs[v.w*64 + lane]); c1 = fmaxf(c1, Hs[v.w*64 + lane + 32]);
        }
        // split + pack (n0,n1) pairs
        __nv_bfloat16 h0 = __float2bfloat16(a0), h1 = __float2bfloat16(c0);
        __nv_bfloat16 l0 = __float2bfloat16(a0 - __bfloat162float(h0));
        __nv_bfloat16 l1 = __float2bfloat16(c0 - __bfloat162float(h1));
        *(__nv_bfloat162*)(smc + MFA_HI + lane*528 + n0*2) = __halves2bfloat162(h0, h1);
        *(__nv_bfloat162*)(smc + MFA_LO + lane*528 + n0*2) = __halves2bfloat162(l0, l1);
        __nv_bfloat16 h2 = __float2bfloat16(a1), h3 = __float2bfloat16(c1);
        __nv_bfloat16 l2 = __float2bfloat16(a1 - __bfloat162float(h2));
        __nv_bfloat16 l3 = __float2bfloat16(c1 - __bfloat162float(h3));
        *(__nv_bfloat162*)(smc + MFA_HI + (lane+32)*528 + n0*2) = __halves2bfloat162(h2, h3);
        *(__nv_bfloat162*)(smc + MFA_LO + (lane+32)*528 + n0*2) = __halves2bfloat162(l2, l3);
    }
    __syncthreads();

    // ---- Phase B: W1 bf16 hi/lo over dead Hs region (128 rows x 32 uint4)
    for (int e = tid; e < 4096; e += 512) {
        int row = e >> 5, q = e & 31;
        *(uint4*)(smc + MFW1HI + row*528 + q*16) = ((const uint4*)(g_w1hi + row*256))[q];
        *(uint4*)(smc + MFW1LO + row*528 + q*16) = ((const uint4*)(g_w1lo + row*256))[q];
    }
    __syncthreads();

    // ---- fc1 HMMA: warps 4(m) x 2(n); warp covers 16 ch x 64 o; k = 256.
    // warps 8..15 duplicate warps 0..7's tiles? No: use 16 warps = 4m x 4n? 
    // 512 threads = 16 warps: warps laid 4(m) x 4(n), warp covers 16 ch x 32 o.
    int m0 = (w >> 2) * 16;          // 4 m-tiles
    int nb = (w & 3) * 32;           // 4 n-strips of 32 o
    uint32_t smb = smem_u32(smc);
    uint32_t a_row_off = (uint32_t)((m0 + (lane & 7) + ((lane >> 3) & 1)*8) * 528
                                    + (lane >> 4) * 16);
    uint32_t aaddr_hi = smb + MFA_HI + a_row_off;
    uint32_t aaddr_lo = smb + MFA_LO + a_row_off;
    uint32_t b_row_off = (uint32_t)((nb + ((lane >> 4) & 1)*8 + (lane & 7)) * 528
                                    + ((lane >> 3) & 1) * 16);
    uint32_t baddr_hi = smb + MFW1HI + b_row_off;
    uint32_t baddr_lo = smb + MFW1LO + b_row_off;

    float acc[4][4];
    #pragma unroll
    for (int nt = 0; nt < 4; nt++)
        #pragma unroll
        for (int k = 0; k < 4; k++) acc[nt][k] = 0.f;

    #pragma unroll 4
    for (int k0 = 0; k0 < 256; k0 += 16) {
        uint32_t ah0, ah1, ah2, ah3, al0, al1, al2, al3;
        LDSM_X4(ah0, ah1, ah2, ah3, aaddr_hi);
        LDSM_X4(al0, al1, al2, al3, aaddr_lo);
        aaddr_hi += 32; aaddr_lo += 32;
        #pragma unroll
        for (int p = 0; p < 2; p++) {
            uint32_t bh0, bh1, bh2, bh3, bl0, bl1, bl2, bl3;
            LDSM_X4(bh0, bh1, bh2, bh3, baddr_hi + p*8448u);
            LDSM_X4(bl0, bl1, bl2, bl3, baddr_lo + p*8448u);
            MMA16816(acc[2*p],   ah0, ah1, ah2, ah3, bh0, bh1);
            MMA16816(acc[2*p],   ah0, ah1, ah2, ah3, bl0, bl1);
            MMA16816(acc[2*p],   al0, al1, al2, al3, bh0, bh1);
            MMA16816(acc[2*p+1], ah0, ah1, ah2, ah3, bh2, bh3);
            MMA16816(acc[2*p+1], ah0, ah1, ah2, ah3, bl2, bl3);
            MMA16816(acc[2*p+1], al0, al1, al2, al3, bh2, bh3);
        }
        baddr_hi += 32; baddr_lo += 32;
    }
    __syncthreads();   // A region dead; Gs overlays it

    // ---- epilogue: bias + relu into Gs[ch][129]
    float* Gs = (float*)smc;
    #pragma unroll
    for (int nt = 0; nt < 4; nt++) {
        int col = nb + nt*8 + 2*tig;
        float bv0 = *(const float*)(smc + MFB1 + col*4);
        float bv1 = *(const float*)(smc + MFB1 + col*4 + 4);
        Gs[(m0 + g)*129 + col]       = fmaxf(acc[nt][0] + bv0, 0.f);
        Gs[(m0 + g)*129 + col + 1]   = fmaxf(acc[nt][1] + bv1, 0.f);
        Gs[(m0 + g + 8)*129 + col]     = fmaxf(acc[nt][2] + bv0, 0.f);
        Gs[(m0 + g + 8)*129 + col + 1] = fmaxf(acc[nt][3] + bv1, 0.f);
    }
    __syncthreads();

    // ---- fc2: warps 0..7, q = w*5 .. w*5+4; lane -> ch = lane, lane+32
    if (w < 8) {
        float acc2[2][5];
        #pragma unroll
        for (int h = 0; h < 2; h++)
            #pragma unroll
            for (int q = 0; q < 5; q++) acc2[h][q] = 0.f;
        #pragma unroll 4
        for (int o = 0; o < 128; o++) {
            float ga = Gs[lane*129 + o];
            float gb = Gs[(lane + 32)*129 + o];
            #pragma unroll
            for (int q = 0; q < 5; q++) {
                float wv = W2s[(w*5 + q)*128 + o];
                acc2[0][q] += ga*wv;
                acc2[1][q] += gb*wv;
            }
        }
        #pragma unroll
        for (int h = 0; h < 2; h++) {
            int cg = ct*64 + lane + h*32;
            #pragma unroll
            for (int q = 0; q < 5; q++)
                out[(b*256 + cg)*40 + w*5 + q] = acc2[h][q] + fc2_b[w*5 + q];
        }
    }
}

extern "C" void kernel_launch(void* const* d_in, const int* in_sizes, int n_in,
                              void* d_out, int out_size) {
    const float* x    = (const float*)d_in[0];
    const float* w1   = (const float*)d_in[1];
    const float* s1   = (const float*)d_in[2];
    const float* t1   = (const float*)d_in[3];
    const float* w2   = (const float*)d_in[4];
    const float* s2   = (const float*)d_in[5];
    const float* t2   = (const float*)d_in[6];
    const float* w3   = (const float*)d_in[7];
    const float* s3   = (const float*)d_in[8];
    const float* t3   = (const float*)d_in[9];
    const float* fc1w = (const float*)d_in[10];
    const float* fc1b = (const float*)d_in[11];
    const float* fc2w = (const float*)d_in[12];
    const float* fc2b = (const float*)d_in[13];
    float* out = (float*)d_out;

    cudaFuncSetAttribute(mlp12_kernel, cudaFuncAttributeMaxDynamicSharedMemorySize, MLP12_SMEM);
    cudaFuncSetAttribute(mlp3h_kernel, cudaFuncAttributeMaxDynamicSharedMemorySize, MLP3H_SMEM);
    cudaFuncSetAttribute(maxfc_kernel, cudaFuncAttributeMaxDynamicSharedMemorySize, MAXFC_SMEM);

    transpose_kernel<<<288, 256>>>(w2, w3, fc1w);
    knn_kernel<<<1024, 256>>>(x);
    mlp12_kernel<<<256, 256, MLP12_SMEM>>>(x, w1, s1, t1, s2, t2);
    mlp3h_kernel<<<256, 256, MLP3H_SMEM>>>(s3, t3);
    maxfc_kernel<<<128, 512, MAXFC_SMEM>>>(fc1b, fc2w, fc2b, out);
}

// round 16
// speedup vs baseline: 1.2266x; 1.0335x over previous
#include <cuda_runtime.h>
#include <cuda_bf16.h>
#include <cstdint>

#define NEG_INF (-1e30f)
#define BB 32
#define NN 256
#define KNB 20

// ---------------- mma.sync m16n8k16 bf16 + ldmatrix (baseline PTX) ----------
#define MMA16816(c, a0, a1, a2, a3, b0, b1) \
    asm volatile("mma.sync.aligned.m16n8k16.row.col.f32.bf16.bf16.f32 " \
        "{%0,%1,%2,%3}, {%4,%5,%6,%7}, {%8,%9}, {%0,%1,%2,%3};" \
        : "+f"((c)[0]), "+f"((c)[1]), "+f"((c)[2]), "+f"((c)[3]) \
        : "r"(a0), "r"(a1), "r"(a2), "r"(a3), "r"(b0), "r"(b1))

#define LDSM_X4(r0, r1, r2, r3, addr) \
    asm volatile("ldmatrix.sync.aligned.m8n8.x4.shared.b16 {%0,%1,%2,%3}, [%4];" \
        : "=r"(r0), "=r"(r1), "=r"(r2), "=r"(r3) : "r"(addr))

__device__ __forceinline__ uint32_t smem_u32(const void* p) {
    uint32_t a;
    asm("{ .reg .u64 t; cvta.to.shared.u64 t, %1; cvt.u32.u64 %0, t; }" : "=r"(a) : "l"(p));
    return a;
}

// ---------------- scratch globals ----------------
__device__ int            g_idx  [BB*NN*KNB];
__device__ float          g_H    [BB*NN*256];
__device__ __nv_bfloat16  g_w3hi [256*128];
__device__ __nv_bfloat16  g_w3lo [256*128];
__device__ __nv_bfloat16  g_w1hi [128*256];
__device__ __nv_bfloat16  g_w1lo [128*256];
__device__ float          g_w2T  [64*128];

// ---------------------------------------------------------------------------
// Kernel 0: weight prep (w2 transpose; w3 and fc1_w bf16 hi/lo splits)
// ---------------------------------------------------------------------------
__global__ __launch_bounds__(256) void transpose_kernel(
    const float* __restrict__ w2, const float* __restrict__ w3,
    const float* __restrict__ fc1w)
{
    int tid = blockIdx.x*256 + threadIdx.x;
    if (tid < 8192) { int c = tid >> 7, o = tid & 127; g_w2T[tid] = w2[o*64 + c]; }
    int t2 = tid - 8192;
    if (t2 >= 0 && t2 < 32768) {
        float v = w3[t2];
        __nv_bfloat16 h = __float2bfloat16(v);
        __nv_bfloat16 l = __float2bfloat16(v - __bfloat162float(h));
        g_w3hi[t2] = h; g_w3lo[t2] = l;
    }
    int t3 = tid - 40960;
    if (t3 >= 0 && t3 < 32768) {
        float v = fc1w[t3];               // already [o][n]
        __nv_bfloat16 h = __float2bfloat16(v);
        __nv_bfloat16 l = __float2bfloat16(v - __bfloat162float(h));
        g_w1hi[t3] = h; g_w1lo[t3] = l;
    }
}

// ---------------------------------------------------------------------------
// Kernel 1: kNN (one row/warp, redux argmax)
// ---------------------------------------------------------------------------
__global__ __launch_bounds__(256) void knn_kernel(const float* __restrict__ x) {
    __shared__ float xs0[NN], xs1[NN], xs2[NN], xxs[NN];
    int b      = blockIdx.x >> 5;
    int n_base = (blockIdx.x & 31) * 8;
    int tid = threadIdx.x;
    {
        float a0 = x[(b*NN + tid)*3 + 0];
        float a1 = x[(b*NN + tid)*3 + 1];
        float a2 = x[(b*NN + tid)*3 + 2];
        xs0[tid] = a0; xs1[tid] = a1; xs2[tid] = a2;
        xxs[tid] = a0*a0 + a1*a1 + a2*a2;
    }
    __syncthreads();
    int w = tid >> 5, lane = tid & 31;
    int i = n_base + w;

    float xi0 = xs0[i], xi1 = xs1[i], xi2 = xs2[i], xxi = xxs[i];
    unsigned m[8];
    #pragma unroll
    for (int t = 0; t < 8; t++) {
        int j = lane + 32*t;
        float dv = 2.f*(xi0*xs0[j] + xi1*xs1[j] + xi2*xs2[j]) - xxi - xxs[j];
        unsigned u = __float_as_uint(dv);
        m[t] = u ^ (unsigned)(((int)u >> 31) | 0x80000000);
    }

    int myj = 0;
    #pragma unroll 4
    for (int kk = 0; kk < KNB; kk++) {
        unsigned bv = m[0]; int bj = lane;
        #pragma unroll
        for (int t = 1; t < 8; t++)
            if (m[t] > bv) { bv = m[t]; bj = lane + 32*t; }
        unsigned vmax = __reduce_max_sync(0xffffffffu, bv);
        unsigned cand = (bv == vmax) ? (unsigned)bj : 0x7fffffffu;
        int jwin = (int)__reduce_min_sync(0xffffffffu, cand);
        if (lane == kk) myj = jwin;
        if ((jwin & 31) == lane) {
            int t = jwin >> 5;
            #pragma unroll
            for (int tt = 0; tt < 8; tt++) if (tt == t) m[tt] = 0u;
        }
    }
    if (lane < KNB) g_idx[(b*NN + i)*KNB + lane] = myj;
}

// ---------------------------------------------------------------------------
// Kernel 2: FUSED mlp (3 -> 64 -> 128 scalar, then 128 -> 256 via HMMA).
// grid = 256 blocks (64-row groups x 2 o-halves), 256 threads, 2 CTA/SM.
// Phase 1-2 scratch (xs, H1s, W2T) overlays the B region (B staged after).
// Layout (bytes):
//   A_hi[64x272] 0 | A_lo 17408 | B_hi[128x272] 34816 | B_lo 69632
//   overlay in B region during phase 1-2: xs@34816 H1s@35584 W2T@51968
//   s3 104448 | t3 104960 ; total 105472
// ---------------------------------------------------------------------------
#define AHI_OFF 0
#define ALO_OFF 17408
#define BHI_OFF 34816
#define BLO_OFF 69632
#define XS_OFF  34816
#define H1S_OFF 35584
#define W2T_OFF 51968
#define S3H_OFF 104448
#define T3H_OFF 104960
#define MLP3H_SMEM 105472

__global__ __launch_bounds__(256, 2) void mlp3h_kernel(
    const float* __restrict__ x,
    const float* __restrict__ w1, const float* __restrict__ s1, const float* __restrict__ t1,
    const float* __restrict__ s2, const float* __restrict__ t2,
    const float* __restrict__ s3, const float* __restrict__ t3)
{
    extern __shared__ char smc[];
    int tid = threadIdx.x;
    int w = tid >> 5, lane = tid & 31;
    int g = lane >> 2, tig = lane & 3;
    int bid = blockIdx.x;
    int row0 = (bid >> 1) * 64;
    int oh = bid & 1;
    int b = row0 >> 8;
    int j0 = row0 & 255;

    float* xs   = (float*)(smc + XS_OFF);
    float* H1s  = (float*)(smc + H1S_OFF);
    float* W2Ts = (float*)(smc + W2T_OFF);

    // ---- phase 0: stage x rows, W2T, s3/t3
    if (tid < 192) xs[tid] = x[b*768 + j0*3 + tid];
    for (int e = tid; e < 2048; e += 256)
        ((float4*)W2Ts)[e] = ((const float4*)g_w2T)[e];
    if (tid < 128) {
        *(float*)(smc + S3H_OFF + tid*4) = s3[oh*128 + tid];
        *(float*)(smc + T3H_OFF + tid*4) = t3[oh*128 + tid];
    }
    __syncthreads();

    int rb = w * 8;   // warp owns 8 rows throughout phases 1-2

    // ---- phase 1: h1 (lane computes outputs lane, lane+32 for 8 rows)
    {
        int o2 = lane + 32;
        float a0 = w1[lane*3], a1 = w1[lane*3+1], a2 = w1[lane*3+2];
        float b0 = w1[o2*3],   b1 = w1[o2*3+1],   b2 = w1[o2*3+2];
        float sa = s1[lane], ta = t1[lane], sb = s1[o2], tb = t1[o2];
        #pragma unroll
        for (int i = 0; i < 8; i++) {
            int row = rb + i;
            float x0 = xs[row*3], x1 = xs[row*3+1], x2 = xs[row*3+2];
            H1s[row*64 + lane]      = fmaxf(sa*(a0*x0 + a1*x1 + a2*x2) + ta, 0.f);
            H1s[row*64 + lane + 32] = fmaxf(sb*(b0*x0 + b1*x1 + b2*x2) + tb, 0.f);
        }
    }
    __syncwarp();

    // ---- phase 2: h2 = w2 @ h1 (lane owns o-chunk lane*4); write A bf16 hi/lo
    {
        float acc[8][4];
        #pragma unroll
        for (int i = 0; i < 8; i++)
            #pragma unroll
            for (int k = 0; k < 4; k++) acc[i][k] = 0.f;
        #pragma unroll 8
        for (int c = 0; c < 64; c++) {
            float4 wv = *(const float4*)&W2Ts[c*128 + lane*4];
            #pragma unroll
            for (int i = 0; i < 8; i++) {
                float h = H1s[(rb+i)*64 + c];
                acc[i][0] += h*wv.x; acc[i][1] += h*wv.y;
                acc[i][2] += h*wv.z; acc[i][3] += h*wv.w;
            }
        }
        float sv[4], tv[4];
        #pragma unroll
        for (int k = 0; k < 4; k++) { sv[k] = s2[lane*4+k]; tv[k] = t2[lane*4+k]; }
        #pragma unroll
        for (int i = 0; i < 8; i++) {
            float o[4];
            #pragma unroll
            for (int k = 0; k < 4; k++)
                o[k] = fmaxf(sv[k]*acc[i][k] + tv[k], 0.f);
            __nv_bfloat16 h[4], l[4];
            #pragma unroll
            for (int k = 0; k < 4; k++) {
                h[k] = __float2bfloat16(o[k]);
                l[k] = __float2bfloat16(o[k] - __bfloat162float(h[k]));
            }
            int boff = (rb + i)*272 + lane*8;   // 4 bf16 = 8 bytes
            *(__nv_bfloat162*)(smc + AHI_OFF + boff)     = __halves2bfloat162(h[0], h[1]);
            *(__nv_bfloat162*)(smc + AHI_OFF + boff + 4) = __halves2bfloat162(h[2], h[3]);
            *(__nv_bfloat162*)(smc + ALO_OFF + boff)     = __halves2bfloat162(l[0], l[1]);
            *(__nv_bfloat162*)(smc + ALO_OFF + boff + 4) = __halves2bfloat162(l[2], l[3]);
        }
    }
    __syncthreads();   // A complete; phase-1 scratch now dead

    // ---- phase 3: stage B (w3 hi/lo, this o-half) over the overlay region
    for (int e = tid; e < 2048; e += 256) {
        int row = e >> 4, q = e & 15;
        *(uint4*)(smc + BHI_OFF + row*272 + q*16) =
            ((const uint4*)(g_w3hi + (oh*128 + row)*128))[q];
        *(uint4*)(smc + BLO_OFF + row*272 + q*16) =
            ((const uint4*)(g_w3lo + (oh*128 + row)*128))[q];
    }
    __syncthreads();

    // ---- phase 4: HMMA (round-15 exact)
    int m0 = (w >> 1) * 16;
    int nb = (w & 1) * 64;

    uint32_t smb = smem_u32(smc);
    uint32_t a_row_off = (uint32_t)((m0 + (lane & 7) + ((lane >> 3) & 1)*8) * 272
                                    + (lane >> 4) * 16);
    uint32_t aaddr_hi = smb + AHI_OFF + a_row_off;
    uint32_t aaddr_lo = smb + ALO_OFF + a_row_off;
    uint32_t b_row_off = (uint32_t)((nb + ((lane >> 4) & 1)*8 + (lane & 7)) * 272
                                    + ((lane >> 3) & 1) * 16);
    uint32_t baddr_hi = smb + BHI_OFF + b_row_off;
    uint32_t baddr_lo = smb + BLO_OFF + b_row_off;

    float acc[8][4];
    #pragma unroll
    for (int nt = 0; nt < 8; nt++)
        #pragma unroll
        for (int k = 0; k < 4; k++) acc[nt][k] = 0.f;

    #pragma unroll
    for (int k0 = 0; k0 < 128; k0 += 16) {
        uint32_t ah0, ah1, ah2, ah3, al0, al1, al2, al3;
        LDSM_X4(ah0, ah1, ah2, ah3, aaddr_hi);
        LDSM_X4(al0, al1, al2, al3, aaddr_lo);
        aaddr_hi += 32; aaddr_lo += 32;
        #pragma unroll
        for (int p = 0; p < 4; p++) {
            uint32_t bh0, bh1, bh2, bh3, bl0, bl1, bl2, bl3;
            LDSM_X4(bh0, bh1, bh2, bh3, baddr_hi + p*4352u);
            LDSM_X4(bl0, bl1, bl2, bl3, baddr_lo + p*4352u);
            MMA16816(acc[2*p],   ah0, ah1, ah2, ah3, bh0, bh1);
            MMA16816(acc[2*p],   ah0, ah1, ah2, ah3, bl0, bl1);
            MMA16816(acc[2*p],   al0, al1, al2, al3, bh0, bh1);
            MMA16816(acc[2*p+1], ah0, ah1, ah2, ah3, bh2, bh3);
            MMA16816(acc[2*p+1], ah0, ah1, ah2, ah3, bl2, bl3);
            MMA16816(acc[2*p+1], al0, al1, al2, al3, bh2, bh3);
        }
        baddr_hi += 32; baddr_lo += 32;
    }

    #pragma unroll
    for (int nt = 0; nt < 8; nt++) {
        int ci = nb + nt*8 + 2*tig;
        float2 sv = *(const float2*)(smc + S3H_OFF + ci*4);
        float2 tv = *(const float2*)(smc + T3H_OFF + ci*4);
        float2 o0, o1;
        o0.x = fmaxf(sv.x*acc[nt][0] + tv.x, 0.f);
        o0.y = fmaxf(sv.y*acc[nt][1] + tv.y, 0.f);
        o1.x = fmaxf(sv.x*acc[nt][2] + tv.x, 0.f);
        o1.y = fmaxf(sv.y*acc[nt][3] + tv.y, 0.f);
        int col = oh*128 + ci;
        *(float2*)&g_H[(row0 + m0 + g)*256 + col]     = o0;
        *(float2*)&g_H[(row0 + m0 + g + 8)*256 + col] = o1;
    }
}

// ---------------------------------------------------------------------------
// Kernel 3: FUSED gather-max + fc1(HMMA bf16 hi/lo) + fc2 (round-15 exact)
// ---------------------------------------------------------------------------
#define MFA_HI  0
#define MFA_LO  33792
#define MFHS    67584
#define MFW1HI  67584
#define MFW1LO  135168
#define MFW2    202752
#define MFB1    223232
#define MAXFC_SMEM 223744

__global__ __launch_bounds__(512) void maxfc_kernel(
    const float* __restrict__ fc1_b,
    const float* __restrict__ fc2_w, const float* __restrict__ fc2_b,
    float* __restrict__ out)
{
    extern __shared__ char smc[];
    float* Hs  = (float*)(smc + MFHS);     // [j 256][c 64]
    float* W2s = (float*)(smc + MFW2);     // [q 40][o 128]
    int b = blockIdx.x >> 2, ct = blockIdx.x & 3;
    int tid = threadIdx.x;
    int w = tid >> 5, lane = tid & 31;
    int g = lane >> 2, tig = lane & 3;

    for (int e = tid; e < 4096; e += 512) {
        int j = e >> 4, q = e & 15;
        ((float4*)Hs)[e] = *(const float4*)(g_H + (b*256 + j)*256 + ct*64 + q*4);
    }
    for (int e = tid; e < 1280; e += 512)
        ((float4*)W2s)[e] = ((const float4*)fc2_w)[e];
    if (tid < 128) *(float*)(smc + MFB1 + tid*4) = fc1_b[tid];
    __syncthreads();

    #pragma unroll 2
    for (int t = 0; t < 16; t += 2) {
        int n0 = w*16 + t, n1 = n0 + 1;
        const int4* ip0 = (const int4*)(g_idx + (b*NN + n0)*KNB);
        const int4* ip1 = (const int4*)(g_idx + (b*NN + n1)*KNB);
        float a0 = NEG_INF, a1 = NEG_INF, c0 = NEG_INF, c1 = NEG_INF;
        #pragma unroll
        for (int q = 0; q < 5; q++) {
            int4 u = ip0[q];
            int4 v = ip1[q];
            a0 = fmaxf(a0, Hs[u.x*64 + lane]); a1 = fmaxf(a1, Hs[u.x*64 + lane + 32]);
            c0 = fmaxf(c0, Hs[v.x*64 + lane]); c1 = fmaxf(c1, Hs[v.x*64 + lane + 32]);
            a0 = fmaxf(a0, Hs[u.y*64 + lane]); a1 = fmaxf(a1, Hs[u.y*64 + lane + 32]);
            c0 = fmaxf(c0, Hs[v.y*64 + lane]); c1 = fmaxf(c1, Hs[v.y*64 + lane + 32]);
            a0 = fmaxf(a0, Hs[u.z*64 + lane]); a1 = fmaxf(a1, Hs[u.z*64 + lane + 32]);
            c0 = fmaxf(c0, Hs[v.z*64 + lane]); c1 = fmaxf(c1, Hs[v.z*64 + lane + 32]);
            a0 = fmaxf(a0, Hs[u.w*64 + lane]); a1 = fmaxf(a1, Hs[u.w*64 + lane + 32]);
            c0 = fmaxf(c0, Hs[v.w*64 + lane]); c1 = fmaxf(c1, Hs[v.w*64 + lane + 32]);
        }
        __nv_bfloat16 h0 = __float2bfloat16(a0), h1 = __float2bfloat16(c0);
        __nv_bfloat16 l0 = __float2bfloat16(a0 - __bfloat162float(h0));
        __nv_bfloat16 l1 = __float2bfloat16(c0 - __bfloat162float(h1));
        *(__nv_bfloat162*)(smc + MFA_HI + lane*528 + n0*2) = __halves2bfloat162(h0, h1);
        *(__nv_bfloat162*)(smc + MFA_LO + lane*528 + n0*2) = __halves2bfloat162(l0, l1);
        __nv_bfloat16 h2 = __float2bfloat16(a1), h3 = __float2bfloat16(c1);
        __nv_bfloat16 l2 = __float2bfloat16(a1 - __bfloat162float(h2));
        __nv_bfloat16 l3 = __float2bfloat16(c1 - __bfloat162float(h3));
        *(__nv_bfloat162*)(smc + MFA_HI + (lane+32)*528 + n0*2) = __halves2bfloat162(h2, h3);
        *(__nv_bfloat162*)(smc + MFA_LO + (lane+32)*528 + n0*2) = __halves2bfloat162(l2, l3);
    }
    __syncthreads();

    for (int e = tid; e < 4096; e += 512) {
        int row = e >> 5, q = e & 31;
        *(uint4*)(smc + MFW1HI + row*528 + q*16) = ((const uint4*)(g_w1hi + row*256))[q];
        *(uint4*)(smc + MFW1LO + row*528 + q*16) = ((const uint4*)(g_w1lo + row*256))[q];
    }
    __syncthreads();

    int m0 = (w >> 2) * 16;
    int nb = (w & 3) * 32;
    uint32_t smb = smem_u32(smc);
    uint32_t a_row_off = (uint32_t)((m0 + (lane & 7) + ((lane >> 3) & 1)*8) * 528
                                    + (lane >> 4) * 16);
    uint32_t aaddr_hi = smb + MFA_HI + a_row_off;
    uint32_t aaddr_lo = smb + MFA_LO + a_row_off;
    uint32_t b_row_off = (uint32_t)((nb + ((lane >> 4) & 1)*8 + (lane & 7)) * 528
                                    + ((lane >> 3) & 1) * 16);
    uint32_t baddr_hi = smb + MFW1HI + b_row_off;
    uint32_t baddr_lo = smb + MFW1LO + b_row_off;

    float acc[4][4];
    #pragma unroll
    for (int nt = 0; nt < 4; nt++)
        #pragma unroll
        for (int k = 0; k < 4; k++) acc[nt][k] = 0.f;

    #pragma unroll 4
    for (int k0 = 0; k0 < 256; k0 += 16) {
        uint32_t ah0, ah1, ah2, ah3, al0, al1, al2, al3;
        LDSM_X4(ah0, ah1, ah2, ah3, aaddr_hi);
        LDSM_X4(al0, al1, al2, al3, aaddr_lo);
        aaddr_hi += 32; aaddr_lo += 32;
        #pragma unroll
        for (int p = 0; p < 2; p++) {
            uint32_t bh0, bh1, bh2, bh3, bl0, bl1, bl2, bl3;
            LDSM_X4(bh0, bh1, bh2, bh3, baddr_hi + p*8448u);
            LDSM_X4(bl0, bl1, bl2, bl3, baddr_lo + p*8448u);
            MMA16816(acc[2*p],   ah0, ah1, ah2, ah3, bh0, bh1);
            MMA16816(acc[2*p],   ah0, ah1, ah2, ah3, bl0, bl1);
            MMA16816(acc[2*p],   al0, al1, al2, al3, bh0, bh1);
            MMA16816(acc[2*p+1], ah0, ah1, ah2, ah3, bh2, bh3);
            MMA16816(acc[2*p+1], ah0, ah1, ah2, ah3, bl2, bl3);
            MMA16816(acc[2*p+1], al0, al1, al2, al3, bh2, bh3);
        }
        baddr_hi += 32; baddr_lo += 32;
    }
    __syncthreads();

    float* Gs = (float*)smc;
    #pragma unroll
    for (int nt = 0; nt < 4; nt++) {
        int col = nb + nt*8 + 2*tig;
        float bv0 = *(const float*)(smc + MFB1 + col*4);
        float bv1 = *(const float*)(smc + MFB1 + col*4 + 4);
        Gs[(m0 + g)*129 + col]       = fmaxf(acc[nt][0] + bv0, 0.f);
        Gs[(m0 + g)*129 + col + 1]   = fmaxf(acc[nt][1] + bv1, 0.f);
        Gs[(m0 + g + 8)*129 + col]     = fmaxf(acc[nt][2] + bv0, 0.f);
        Gs[(m0 + g + 8)*129 + col + 1] = fmaxf(acc[nt][3] + bv1, 0.f);
    }
    __syncthreads();

    if (w < 8) {
        float acc2[2][5];
        #pragma unroll
        for (int h = 0; h < 2; h++)
            #pragma unroll
            for (int q = 0; q < 5; q++) acc2[h][q] = 0.f;
        #pragma unroll 4
        for (int o = 0; o < 128; o++) {
            float ga = Gs[lane*129 + o];
            float gb = Gs[(lane + 32)*129 + o];
            #pragma unroll
            for (int q = 0; q < 5; q++) {
                float wv = W2s[(w*5 + q)*128 + o];
                acc2[0][q] += ga*wv;
                acc2[1][q] += gb*wv;
            }
        }
        #pragma unroll
        for (int h = 0; h < 2; h++) {
            int cg = ct*64 + lane + h*32;
            #pragma unroll
            for (int q = 0; q < 5; q++)
                out[(b*256 + cg)*40 + w*5 + q] = acc2[h][q] + fc2_b[w*5 + q];
        }
    }
}

extern "C" void kernel_launch(void* const* d_in, const int* in_sizes, int n_in,
                              void* d_out, int out_size) {
    const float* x    = (const float*)d_in[0];
    const float* w1   = (const float*)d_in[1];
    const float* s1   = (const float*)d_in[2];
    const float* t1   = (const float*)d_in[3];
    const float* w2   = (const float*)d_in[4];
    const float* s2   = (const float*)d_in[5];
    const float* t2   = (const float*)d_in[6];
    const float* w3   = (const float*)d_in[7];
    const float* s3   = (const float*)d_in[8];
    const float* t3   = (const float*)d_in[9];
    const float* fc1w = (const float*)d_in[10];
    const float* fc1b = (const float*)d_in[11];
    const float* fc2w = (const float*)d_in[12];
    const float* fc2b = (const float*)d_in[13];
    float* out = (float*)d_out;

    cudaFuncSetAttribute(mlp3h_kernel, cudaFuncAttributeMaxDynamicSharedMemorySize, MLP3H_SMEM);
    cudaFuncSetAttribute(maxfc_kernel, cudaFuncAttributeMaxDynamicSharedMemorySize, MAXFC_SMEM);

    transpose_kernel<<<288, 256>>>(w2, w3, fc1w);
    knn_kernel<<<1024, 256>>>(x);
    mlp3h_kernel<<<256, 256, MLP3H_SMEM>>>(x, w1, s1, t1, s2, t2, s3, t3);
    maxfc_kernel<<<128, 512, MAXFC_SMEM>>>(fc1b, fc2w, fc2b, out);
}